// round 15
// baseline (speedup 1.0000x reference)
#include <cuda_runtime.h>

// cumprod along dim 1 of a (4096, 8192) fp32 matrix.  [R8 champion + fused
// early local prefixes]
// CTA-per-row, 256 threads = 8 warps. Warp w owns floats [1024w, 1024w+1024);
// lane L owns float4 L of each 128-float chunk -> loads AND stores natively
// coalesced, values register-resident end-to-end.
// Pre-barrier: local 3-FMUL prefixes folded IN PLACE while accumulating the
// thread's segment product from the v.w chain (no separate tree product),
// then butterfly-reduce to the warp segment total. Post-barrier: per-chunk
// warp scan + scale + store with the cross-warp prefix folded into the carry.

#define ROW_LEN  8192
#define THREADS  256
#define NWARPS   8
#define CHUNKS   8                    // 128-float chunks per warp segment
#define SEG_VEC  256                  // float4 per warp segment

__global__ void __launch_bounds__(THREADS, 5)
cumprod_dim1_kernel(const float* __restrict__ x, float* __restrict__ y) {
    __shared__ float wtot[NWARPS];

    const int t    = threadIdx.x;
    const int lane = t & 31;
    const int w    = t >> 5;

    const size_t row_off = (size_t)blockIdx.x * ROW_LEN;
    const float4* __restrict__ xin  = reinterpret_cast<const float4*>(x + row_off);
    float4* __restrict__       yout = reinterpret_cast<float4*>(y + row_off);

    const int seg = w * SEG_VEC;      // float4 base of this warp's segment

    // ---- front-batched loads: 8 LDG.128 in flight ----
    float4 vals[CHUNKS];
    #pragma unroll
    for (int c = 0; c < CHUNKS; c++)
        vals[c] = __ldcs(&xin[seg + c * 32 + lane]);

    // ---- pre-barrier: fold local prefixes in place, accumulate totals ----
    float tp = 1.0f;
    #pragma unroll
    for (int c = 0; c < CHUNKS; c++) {
        float4 v = vals[c];
        v.y *= v.x;
        v.z *= v.y;
        v.w *= v.z;
        vals[c] = v;
        tp *= v.w;                    // thread's chunk total, chained
    }
    #pragma unroll
    for (int o = 1; o < 32; o <<= 1)
        tp *= __shfl_xor_sync(0xffffffffu, tp, o);
    if (lane == 0) wtot[w] = tp;
    __syncthreads();

    // ---- cross-warp exclusive prefix, folded into the running carry ----
    float carry = 1.0f;
    #pragma unroll
    for (int ww = 0; ww < NWARPS - 1; ww++) {
        float wt = wtot[ww];
        if (ww < w) carry *= wt;
    }

    // ---- post-barrier: per-chunk warp scan + scale + store ----
    #pragma unroll
    for (int c = 0; c < CHUNKS; c++) {
        float4 v = vals[c];           // local prefixes already applied

        // warp inclusive scan (product) of per-thread chunk totals
        float s = v.w;
        #pragma unroll
        for (int o = 1; o < 32; o <<= 1) {
            float tv = __shfl_up_sync(0xffffffffu, s, o);
            if (lane >= o) s *= tv;
        }
        float e   = __shfl_up_sync(0xffffffffu, s, 1);
        if (lane == 0) e = 1.0f;
        float tot = __shfl_sync(0xffffffffu, s, 31);

        const float ce = carry * e;   // global exclusive prefix for this thread
        v.x *= ce; v.y *= ce; v.z *= ce; v.w *= ce;
        __stcs(&yout[seg + c * 32 + lane], v);

        carry *= tot;
    }
}

extern "C" void kernel_launch(void* const* d_in, const int* in_sizes, int n_in,
                              void* d_out, int out_size) {
    const float* x = (const float*)d_in[0];
    float* y = (float*)d_out;
    const int rows = in_sizes[0] / ROW_LEN;   // 4096
    cumprod_dim1_kernel<<<rows, THREADS>>>(x, y);
}

// round 16
// speedup vs baseline: 1.0022x; 1.0022x over previous
#include <cuda_runtime.h>

// cumprod along dim 1 of a (4096, 8192) fp32 matrix.  [FINAL — R8/R14 champion]
// CTA-per-row, 256 threads = 8 warps. Warp w owns floats [1024w, 1024w+1024);
// lane L owns float4 L of each 128-float chunk -> loads AND stores natively
// coalesced, values register-resident end-to-end. Segment totals are computed
// EARLY (order-independent tree product + butterfly reduce), so the barrier
// fires right after the loads; the scan+scale+store pass runs after it with
// the cross-warp prefix already folded into the carry.
//
// Plateau evidence (15 rounds): this shape = 43.5-43.8 us bench / 35.3-35.5 us
// kernel / 74-76% DRAM (~5.95 TB/s mixed R/W). Occupancy 33-87%, MLP 2-16,
// smem-staged / two-pass-L2 / persistent (atomic & static) / cross-row
// register pipelining / FMUL fusion all regress or tie: the binding resource
// is the HBM mixed-stream throughput on irreducible 2x128 MB traffic.

#define ROW_LEN  8192
#define THREADS  256
#define NWARPS   8
#define CHUNKS   8                    // 128-float chunks per warp segment
#define SEG_VEC  256                  // float4 per warp segment

__global__ void __launch_bounds__(THREADS, 5)
cumprod_dim1_kernel(const float* __restrict__ x, float* __restrict__ y) {
    __shared__ float wtot[NWARPS];

    const int t    = threadIdx.x;
    const int lane = t & 31;
    const int w    = t >> 5;

    const size_t row_off = (size_t)blockIdx.x * ROW_LEN;
    const float4* __restrict__ xin  = reinterpret_cast<const float4*>(x + row_off);
    float4* __restrict__       yout = reinterpret_cast<float4*>(y + row_off);

    const int seg = w * SEG_VEC;      // float4 base of this warp's segment

    // ---- front-batched loads: 8 LDG.128 in flight ----
    float4 vals[CHUNKS];
    #pragma unroll
    for (int c = 0; c < CHUNKS; c++)
        vals[c] = __ldcs(&xin[seg + c * 32 + lane]);

    // ---- EARLY segment total: order-independent tree product ----
    float tp = 1.0f;
    #pragma unroll
    for (int c = 0; c < CHUNKS; c++) {
        float4 v = vals[c];
        tp *= (v.x * v.y) * (v.z * v.w);
    }
    #pragma unroll
    for (int o = 1; o < 32; o <<= 1)
        tp *= __shfl_xor_sync(0xffffffffu, tp, o);
    if (lane == 0) wtot[w] = tp;
    __syncthreads();

    // ---- cross-warp exclusive prefix, folded into the running carry ----
    float carry = 1.0f;
    #pragma unroll
    for (int ww = 0; ww < NWARPS - 1; ww++) {
        float wt = wtot[ww];
        if (ww < w) carry *= wt;
    }

    // ---- scan + scale + store, single pass ----
    #pragma unroll
    for (int c = 0; c < CHUNKS; c++) {
        float4 v = vals[c];
        // local inclusive prefix within the thread's 4 elements
        v.y *= v.x;
        v.z *= v.y;
        v.w *= v.z;

        // warp inclusive scan (product) of per-thread totals
        float s = v.w;
        #pragma unroll
        for (int o = 1; o < 32; o <<= 1) {
            float tv = __shfl_up_sync(0xffffffffu, s, o);
            if (lane >= o) s *= tv;
        }
        float e   = __shfl_up_sync(0xffffffffu, s, 1);
        if (lane == 0) e = 1.0f;
        float tot = __shfl_sync(0xffffffffu, s, 31);

        const float ce = carry * e;   // global exclusive prefix for this thread
        v.x *= ce; v.y *= ce; v.z *= ce; v.w *= ce;
        __stcs(&yout[seg + c * 32 + lane], v);

        carry *= tot;
    }
}

extern "C" void kernel_launch(void* const* d_in, const int* in_sizes, int n_in,
                              void* d_out, int out_size) {
    const float* x = (const float*)d_in[0];
    float* y = (float*)d_out;
    const int rows = in_sizes[0] / ROW_LEN;   // 4096
    cumprod_dim1_kernel<<<rows, THREADS>>>(x, y);
}

// round 17
// speedup vs baseline: 1.0044x; 1.0022x over previous
#include <cuda_runtime.h>

// cumprod along dim 1 of a (4096, 8192) fp32 matrix.  [FINAL — converged]
// CTA-per-row, 256 threads = 8 warps. Warp w owns floats [1024w, 1024w+1024);
// lane L owns float4 L of each 128-float chunk -> loads AND stores natively
// coalesced, values register-resident end-to-end. Segment totals are computed
// EARLY (order-independent tree product + butterfly reduce), so the barrier
// fires right after the loads; the scan+scale+store pass runs after it with
// the cross-warp prefix already folded into the carry.
//
// Convergence evidence (16 rounds): identical binary measures 43.5-44.0 us
// bench / 35.3-36.3 us kernel / 73.5-75.7% DRAM across runs (±1.2% noise,
// matching the documented LTS run-to-run variation). All structural
// alternatives (occupancy 33-87%, MLP 2-16, smem-staged, two-pass-L2,
// persistent x3, cross-row register pipelining) regress 2-6 us; instruction-
// path changes are sub-noise. Traffic (2 x 128 MB) is irreducible; the
// binding resource is mixed 1:1 R/W HBM throughput (~6 TB/s practical).

#define ROW_LEN  8192
#define THREADS  256
#define NWARPS   8
#define CHUNKS   8                    // 128-float chunks per warp segment
#define SEG_VEC  256                  // float4 per warp segment

__global__ void __launch_bounds__(THREADS, 5)
cumprod_dim1_kernel(const float* __restrict__ x, float* __restrict__ y) {
    __shared__ float wtot[NWARPS];

    const int t    = threadIdx.x;
    const int lane = t & 31;
    const int w    = t >> 5;

    const size_t row_off = (size_t)blockIdx.x * ROW_LEN;
    const float4* __restrict__ xin  = reinterpret_cast<const float4*>(x + row_off);
    float4* __restrict__       yout = reinterpret_cast<float4*>(y + row_off);

    const int seg = w * SEG_VEC;      // float4 base of this warp's segment

    // ---- front-batched loads: 8 LDG.128 in flight ----
    float4 vals[CHUNKS];
    #pragma unroll
    for (int c = 0; c < CHUNKS; c++)
        vals[c] = __ldcs(&xin[seg + c * 32 + lane]);

    // ---- EARLY segment total: order-independent tree product ----
    float tp = 1.0f;
    #pragma unroll
    for (int c = 0; c < CHUNKS; c++) {
        float4 v = vals[c];
        tp *= (v.x * v.y) * (v.z * v.w);
    }
    #pragma unroll
    for (int o = 1; o < 32; o <<= 1)
        tp *= __shfl_xor_sync(0xffffffffu, tp, o);
    if (lane == 0) wtot[w] = tp;
    __syncthreads();

    // ---- cross-warp exclusive prefix, folded into the running carry ----
    float carry = 1.0f;
    #pragma unroll
    for (int ww = 0; ww < NWARPS - 1; ww++) {
        float wt = wtot[ww];
        if (ww < w) carry *= wt;
    }

    // ---- scan + scale + store, single pass ----
    #pragma unroll
    for (int c = 0; c < CHUNKS; c++) {
        float4 v = vals[c];
        // local inclusive prefix within the thread's 4 elements
        v.y *= v.x;
        v.z *= v.y;
        v.w *= v.z;

        // warp inclusive scan (product) of per-thread totals
        float s = v.w;
        #pragma unroll
        for (int o = 1; o < 32; o <<= 1) {
            float tv = __shfl_up_sync(0xffffffffu, s, o);
            if (lane >= o) s *= tv;
        }
        float e   = __shfl_up_sync(0xffffffffu, s, 1);
        if (lane == 0) e = 1.0f;
        float tot = __shfl_sync(0xffffffffu, s, 31);

        const float ce = carry * e;   // global exclusive prefix for this thread
        v.x *= ce; v.y *= ce; v.z *= ce; v.w *= ce;
        __stcs(&yout[seg + c * 32 + lane], v);

        carry *= tot;
    }
}

extern "C" void kernel_launch(void* const* d_in, const int* in_sizes, int n_in,
                              void* d_out, int out_size) {
    const float* x = (const float*)d_in[0];
    float* y = (float*)d_out;
    const int rows = in_sizes[0] / ROW_LEN;   // 4096
    cumprod_dim1_kernel<<<rows, THREADS>>>(x, y);
}